// round 16
// baseline (speedup 1.0000x reference)
#include <cuda_runtime.h>
#include <cuda_fp16.h>
#include <cstdint>

// Problem constants
#define MTOT   8192          // B*S
#define IN_CH  256
#define NEXP   8
#define NBASIS 13
#define KTOT   2048          // IN_CH * NEXP
#define NTOT   256           // OUT

// Scratch (L2-resident between launches)
__device__ __half g_A[(size_t)MTOT * KTOT];    // expert outputs [m][k], fp16
__device__ __half g_GB[(size_t)KTOT * NTOT];   // gates blocked:
// [nblk(4)][kt(32)][kl(64)][nl(64)] — each 64x64 tile contiguous (8KB)

// ---------------------------------------------------------------------------
// Prep kernel: blocks 0..255 -> softmax gates (blocked layout)
//              blocks 256..  -> spline eval + expert combine (1 eval/thread)
// ---------------------------------------------------------------------------
__global__ void prep_kernel(const float* __restrict__ gw,
                            const float* __restrict__ x,
                            const float* __restrict__ coeff) {
    if (blockIdx.x < 256) {
        int t = blockIdx.x * 256 + threadIdx.x;   // t = i*256 + o
        int o = t & 255;
        int i = t >> 8;
        const float4* g4 = (const float4*)(gw + (size_t)t * NEXP);
        float4 va = g4[0], vb = g4[1];
        float v[NEXP] = {va.x, va.y, va.z, va.w, vb.x, vb.y, vb.z, vb.w};
        float mx = v[0];
#pragma unroll
        for (int e = 1; e < NEXP; e++) mx = fmaxf(mx, v[e]);
        float s = 0.f;
#pragma unroll
        for (int e = 0; e < NEXP; e++) { v[e] = __expf(v[e] - mx); s += v[e]; }
        float inv = 1.0f / s;
        int nblk = o >> 6, nl = o & 63;
#pragma unroll
        for (int e = 0; e < NEXP; e++) {
            int k = i * NEXP + e;
            int kt = k >> 6, kl = k & 63;
            g_GB[(size_t)((nblk * 32 + kt) * 64 + kl) * 64 + nl] =
                __float2half(v[e] * inv);
        }
        return;
    }

    // ---- eval path: one eval8 per thread, fully coalesced I/O ----
    __shared__ uint4 Cth[NBASIS];  // fp16 coeff table rows (8 halves = 16B)
    int tid = threadIdx.x;
    if (tid < NBASIS * NEXP) {
        int e = tid & 7, n = tid >> 3;
        ((__half*)Cth)[n * 8 + e] = __float2half(coeff[e * NBASIS + n]);
    }
    __syncthreads();

    int u = (blockIdx.x - 256) * 256 + tid;   // u = m*256 + i
    float xc = x[u];
    xc = fminf(fmaxf(xc, -1.0f), 1.0f - 1e-6f);
    float uu = (xc + 1.0f) * 5.0f;
    int i0 = (int)uu;
    i0 = i0 > 9 ? 9 : (i0 < 0 ? 0 : i0);
    uu -= (float)i0;
    float om = 1.0f - uu;
    float u2 = uu * uu, u3 = u2 * uu;
    float b0 = om * om * om * (1.0f / 6.0f);
    float b1 = (3.0f * u3 - 6.0f * u2 + 4.0f) * (1.0f / 6.0f);
    float b2 = (-3.0f * u3 + 3.0f * u2 + 3.0f * uu + 1.0f) * (1.0f / 6.0f);
    float b3 = u3 * (1.0f / 6.0f);
    half2 w0 = __float2half2_rn(b0), w1 = __float2half2_rn(b1);
    half2 w2 = __float2half2_rn(b2), w3 = __float2half2_rn(b3);
    union { uint4 v; half2 h[4]; } c0, c1, c2, c3, out;
    c0.v = Cth[i0]; c1.v = Cth[i0 + 1]; c2.v = Cth[i0 + 2]; c3.v = Cth[i0 + 3];
#pragma unroll
    for (int p = 0; p < 4; p++) {
        half2 a = __hmul2(w0, c0.h[p]);
        a = __hfma2(w1, c1.h[p], a);
        a = __hfma2(w2, c2.h[p], a);
        out.h[p] = __hfma2(w3, c3.h[p], a);
    }
    *(uint4*)(g_A + (size_t)u * NEXP) = out.v;   // warp: 512B contiguous
}

// ---------------------------------------------------------------------------
// Pure GEMM (R13 shape; NSTAGE=4 + CP_WAIT(2) for deeper load tolerance;
// single top barrier per K-step — writer targets (kt+3)%4 == (kt-1)%4,
// ordered by the top barrier of step kt).
// BM=128 BN=64 BK=64, 4 fat warps (32x64 each).
// ---------------------------------------------------------------------------
#define BM  128
#define BN  64
#define BK  64
#define NSTAGE 4
#define AKP 72    // A smem row stride (halves), conflict-free for ldmatrix
#define BNP 72
#define A_ST (BM * AKP * 2)              // 18432 B
#define B_ST (BK * BNP * 2)              // 9216 B
#define STG  (A_ST + B_ST)               // 27648 B per stage
#define SMEM_NEED (NSTAGE * STG)         // 110592 B (x2 CTAs = 221KB <= 228KB)

__device__ __forceinline__ uint32_t smem_addr(const void* p) {
    return (uint32_t)__cvta_generic_to_shared(p);
}

#define CP_ASYNC16(dst, src) \
    asm volatile("cp.async.cg.shared.global [%0], [%1], 16;" \
                 :: "r"(dst), "l"(src))
#define CP_COMMIT()  asm volatile("cp.async.commit_group;")
#define CP_WAIT(n)   asm volatile("cp.async.wait_group %0;" :: "n"(n) : "memory")

__device__ __forceinline__ void mma16816(float* d, const uint32_t* a,
                                         uint32_t b0, uint32_t b1) {
    asm volatile(
        "mma.sync.aligned.m16n8k16.row.col.f32.f16.f16.f32 "
        "{%0,%1,%2,%3}, {%4,%5,%6,%7}, {%8,%9}, {%0,%1,%2,%3};"
        : "+f"(d[0]), "+f"(d[1]), "+f"(d[2]), "+f"(d[3])
        : "r"(a[0]), "r"(a[1]), "r"(a[2]), "r"(a[3]), "r"(b0), "r"(b1));
}

__device__ __forceinline__ void ldm_x4(uint32_t* r, uint32_t ad) {
    asm volatile("ldmatrix.sync.aligned.m8n8.x4.shared.b16 {%0,%1,%2,%3}, [%4];"
                 : "=r"(r[0]), "=r"(r[1]), "=r"(r[2]), "=r"(r[3]) : "r"(ad));
}
__device__ __forceinline__ void ldm_x4t(uint32_t* r, uint32_t ad) {
    asm volatile("ldmatrix.sync.aligned.m8n8.x4.trans.shared.b16 {%0,%1,%2,%3}, [%4];"
                 : "=r"(r[0]), "=r"(r[1]), "=r"(r[2]), "=r"(r[3]) : "r"(ad));
}

__global__ void __launch_bounds__(128, 2)
gemm_kernel(float* __restrict__ C) {
    extern __shared__ char S[];

    const int tid  = threadIdx.x;
    const int lane = tid & 31;
    const int warp = tid >> 5;
    const int wm = warp * 32;          // 4 warps along M, each owns 32x64
    const int g  = lane >> 2;
    const int c2 = (lane & 3) * 2;

    const int m0 = blockIdx.x * BM;
    const int n0 = blockIdx.y * BN;

    const __half* Ag = g_A + (size_t)m0 * KTOT;
    const __half* Bg = g_GB + (size_t)(n0 >> 6) * 32 * 4096;  // per-kt 8KB tiles

    const int lr = lane & 15;
    const int hc = (lane >> 4) * 8;

    float acc[2][8][4];
#pragma unroll
    for (int mi = 0; mi < 2; mi++)
#pragma unroll
        for (int jn = 0; jn < 8; jn++)
#pragma unroll
            for (int q = 0; q < 4; q++) acc[mi][jn][q] = 0.f;

    const int NK = KTOT / BK;   // 32

    // prologue: issue stages 0..2
#pragma unroll
    for (int st = 0; st < NSTAGE - 1; st++) {
        char* base = S + st * STG;
#pragma unroll
        for (int j = 0; j < 8; j++) {
            int c = j * 128 + tid;
            int r = c >> 3, co = c & 7;
            CP_ASYNC16(smem_addr(base + (r * AKP + co * 8) * 2),
                       Ag + (size_t)r * KTOT + st * BK + co * 8);
        }
#pragma unroll
        for (int j = 0; j < 4; j++) {
            int c = j * 128 + tid;
            CP_ASYNC16(smem_addr(base + A_ST + ((c >> 3) * BNP + (c & 7) * 8) * 2),
                       Bg + (size_t)st * 4096 + c * 8);
        }
        CP_COMMIT();
    }

    for (int kt = 0; kt < NK; kt++) {
        // stage kt must be resident; allow up to 2 younger groups in flight
        if (kt < NK - 2)      { CP_WAIT(2); }
        else if (kt < NK - 1) { CP_WAIT(1); }
        else                  { CP_WAIT(0); }
        __syncthreads();   // orders stage-kt visibility AND buffer reuse

        // issue stage kt+3
        if (kt + 3 < NK) {
            char* base = S + ((kt + 3) % NSTAGE) * STG;
#pragma unroll
            for (int j = 0; j < 8; j++) {
                int c = j * 128 + tid;
                int r = c >> 3, co = c & 7;
                CP_ASYNC16(smem_addr(base + (r * AKP + co * 8) * 2),
                           Ag + (size_t)r * KTOT + (kt + 3) * BK + co * 8);
            }
#pragma unroll
            for (int j = 0; j < 4; j++) {
                int c = j * 128 + tid;
                CP_ASYNC16(smem_addr(base + A_ST +
                                     ((c >> 3) * BNP + (c & 7) * 8) * 2),
                           Bg + (size_t)(kt + 3) * 4096 + c * 8);
            }
            CP_COMMIT();
        }

        const __half* Asb = (const __half*)(S + (kt % NSTAGE) * STG);
        const __half* Bsb = (const __half*)(S + (kt % NSTAGE) * STG + A_ST);

        // register double-buffered fragments: load s+1 before MMAs of s
        uint32_t af[2][2][4], bf[2][4][4];
#pragma unroll
        for (int mi = 0; mi < 2; mi++)
            ldm_x4(af[0][mi], smem_addr(Asb + (wm + mi * 16 + lr) * AKP + hc));
#pragma unroll
        for (int j4 = 0; j4 < 4; j4++)
            ldm_x4t(bf[0][j4], smem_addr(Bsb + lr * BNP + j4 * 16 + hc));

#pragma unroll
        for (int s = 0; s < 4; s++) {
            const int cur = s & 1, nxt = cur ^ 1;
            if (s < 3) {
#pragma unroll
                for (int mi = 0; mi < 2; mi++)
                    ldm_x4(af[nxt][mi], smem_addr(Asb + (wm + mi * 16 + lr) * AKP
                                                      + (s + 1) * 16 + hc));
#pragma unroll
                for (int j4 = 0; j4 < 4; j4++)
                    ldm_x4t(bf[nxt][j4], smem_addr(Bsb + ((s + 1) * 16 + lr) * BNP
                                                       + j4 * 16 + hc));
            }
#pragma unroll
            for (int mi = 0; mi < 2; mi++)
#pragma unroll
                for (int j4 = 0; j4 < 4; j4++) {
                    mma16816(acc[mi][2 * j4 + 0], af[cur][mi],
                             bf[cur][j4][0], bf[cur][j4][1]);
                    mma16816(acc[mi][2 * j4 + 1], af[cur][mi],
                             bf[cur][j4][2], bf[cur][j4][3]);
                }
        }
        // no bottom barrier: next iteration's top barrier protects reuse
    }

    // epilogue: warp owns rows [wm, wm+32) x all 64 cols
#pragma unroll
    for (int mi = 0; mi < 2; mi++) {
#pragma unroll
        for (int jn = 0; jn < 8; jn++) {
            int row = m0 + wm + mi * 16 + g;
            int col = n0 + jn * 8 + c2;
            float2 v0 = make_float2(acc[mi][jn][0], acc[mi][jn][1]);
            float2 v1 = make_float2(acc[mi][jn][2], acc[mi][jn][3]);
            *(float2*)&C[(size_t)row * NTOT + col]       = v0;
            *(float2*)&C[(size_t)(row + 8) * NTOT + col] = v1;
        }
    }
}

// ---------------------------------------------------------------------------
extern "C" void kernel_launch(void* const* d_in, const int* in_sizes, int n_in,
                              void* d_out, int out_size) {
    (void)in_sizes; (void)n_in; (void)out_size;
    const float* x     = (const float*)d_in[0];   // (4,2048,256) f32
    const float* coeff = (const float*)d_in[1];   // (8,13) f32
    const float* gw    = (const float*)d_in[2];   // (256,256,8) f32
    float* out = (float*)d_out;                   // (4,2048,256) f32

    cudaFuncSetAttribute(gemm_kernel,
                         cudaFuncAttributeMaxDynamicSharedMemorySize, SMEM_NEED);

    prep_kernel<<<256 + MTOT * IN_CH / 256, 256>>>(gw, x, coeff);
    dim3 grid(MTOT / BM, NTOT / BN);
    gemm_kernel<<<grid, 128, SMEM_NEED>>>(out);
}

// round 17
// speedup vs baseline: 1.1067x; 1.1067x over previous
#include <cuda_runtime.h>
#include <cuda_fp16.h>
#include <cstdint>

// Problem constants
#define MTOT   8192          // B*S
#define IN_CH  256
#define NEXP   8
#define NBASIS 13
#define KTOT   2048          // IN_CH * NEXP
#define NTOT   256           // OUT

// Scratch (L2-resident between launches)
__device__ __half g_A[(size_t)MTOT * KTOT];    // expert outputs [m][k], fp16
__device__ __half g_GB[(size_t)KTOT * NTOT];   // gates blocked:
// [nblk(4)][kt(32)][kl(64)][nl(64)] — each 64x64 tile contiguous (8KB)

// ---------------------------------------------------------------------------
// Prep kernel: blocks 0..255 -> softmax gates (blocked layout)
//              blocks 256..  -> spline eval + expert combine (1 eval/thread)
// ---------------------------------------------------------------------------
__global__ void prep_kernel(const float* __restrict__ gw,
                            const float* __restrict__ x,
                            const float* __restrict__ coeff) {
    if (blockIdx.x < 256) {
        int t = blockIdx.x * 256 + threadIdx.x;   // t = i*256 + o
        int o = t & 255;
        int i = t >> 8;
        const float4* g4 = (const float4*)(gw + (size_t)t * NEXP);
        float4 va = g4[0], vb = g4[1];
        float v[NEXP] = {va.x, va.y, va.z, va.w, vb.x, vb.y, vb.z, vb.w};
        float mx = v[0];
#pragma unroll
        for (int e = 1; e < NEXP; e++) mx = fmaxf(mx, v[e]);
        float s = 0.f;
#pragma unroll
        for (int e = 0; e < NEXP; e++) { v[e] = __expf(v[e] - mx); s += v[e]; }
        float inv = 1.0f / s;
        int nblk = o >> 6, nl = o & 63;
#pragma unroll
        for (int e = 0; e < NEXP; e++) {
            int k = i * NEXP + e;
            int kt = k >> 6, kl = k & 63;
            g_GB[(size_t)((nblk * 32 + kt) * 64 + kl) * 64 + nl] =
                __float2half(v[e] * inv);
        }
        return;
    }

    // ---- eval path: one eval8 per thread, fully coalesced I/O ----
    __shared__ uint4 Cth[NBASIS];  // fp16 coeff table rows (8 halves = 16B)
    int tid = threadIdx.x;
    if (tid < NBASIS * NEXP) {
        int e = tid & 7, n = tid >> 3;
        ((__half*)Cth)[n * 8 + e] = __float2half(coeff[e * NBASIS + n]);
    }
    __syncthreads();

    int u = (blockIdx.x - 256) * 256 + tid;   // u = m*256 + i
    float xc = x[u];
    xc = fminf(fmaxf(xc, -1.0f), 1.0f - 1e-6f);
    float uu = (xc + 1.0f) * 5.0f;
    int i0 = (int)uu;
    i0 = i0 > 9 ? 9 : (i0 < 0 ? 0 : i0);
    uu -= (float)i0;
    float om = 1.0f - uu;
    float u2 = uu * uu, u3 = u2 * uu;
    float b0 = om * om * om * (1.0f / 6.0f);
    float b1 = (3.0f * u3 - 6.0f * u2 + 4.0f) * (1.0f / 6.0f);
    float b2 = (-3.0f * u3 + 3.0f * u2 + 3.0f * uu + 1.0f) * (1.0f / 6.0f);
    float b3 = u3 * (1.0f / 6.0f);
    half2 w0 = __float2half2_rn(b0), w1 = __float2half2_rn(b1);
    half2 w2 = __float2half2_rn(b2), w3 = __float2half2_rn(b3);
    union { uint4 v; half2 h[4]; } c0, c1, c2, c3, out;
    c0.v = Cth[i0]; c1.v = Cth[i0 + 1]; c2.v = Cth[i0 + 2]; c3.v = Cth[i0 + 3];
#pragma unroll
    for (int p = 0; p < 4; p++) {
        half2 a = __hmul2(w0, c0.h[p]);
        a = __hfma2(w1, c1.h[p], a);
        a = __hfma2(w2, c2.h[p], a);
        out.h[p] = __hfma2(w3, c3.h[p], a);
    }
    *(uint4*)(g_A + (size_t)u * NEXP) = out.v;   // warp: 512B contiguous
}

// ---------------------------------------------------------------------------
// Pure GEMM (best-measured config, R13): C[m][o] = sum_k A[m][k] G[k][o].
// BM=128 BN=64 BK=64, 4 fat warps (32x64 each), 3-stage cp.async pipeline,
// register double-buffered fragments.
// ---------------------------------------------------------------------------
#define BM  128
#define BN  64
#define BK  64
#define NSTAGE 3
#define AKP 72    // A smem row stride (halves), conflict-free for ldmatrix
#define BNP 72
#define A_ST (BM * AKP * 2)              // 18432 B
#define B_ST (BK * BNP * 2)              // 9216 B
#define STG  (A_ST + B_ST)               // 27648 B per stage
#define SMEM_NEED (NSTAGE * STG)         // 82944 B

__device__ __forceinline__ uint32_t smem_addr(const void* p) {
    return (uint32_t)__cvta_generic_to_shared(p);
}

#define CP_ASYNC16(dst, src) \
    asm volatile("cp.async.cg.shared.global [%0], [%1], 16;" \
                 :: "r"(dst), "l"(src))
#define CP_COMMIT()  asm volatile("cp.async.commit_group;")
#define CP_WAIT(n)   asm volatile("cp.async.wait_group %0;" :: "n"(n) : "memory")

__device__ __forceinline__ void mma16816(float* d, const uint32_t* a,
                                         uint32_t b0, uint32_t b1) {
    asm volatile(
        "mma.sync.aligned.m16n8k16.row.col.f32.f16.f16.f32 "
        "{%0,%1,%2,%3}, {%4,%5,%6,%7}, {%8,%9}, {%0,%1,%2,%3};"
        : "+f"(d[0]), "+f"(d[1]), "+f"(d[2]), "+f"(d[3])
        : "r"(a[0]), "r"(a[1]), "r"(a[2]), "r"(a[3]), "r"(b0), "r"(b1));
}

__device__ __forceinline__ void ldm_x4(uint32_t* r, uint32_t ad) {
    asm volatile("ldmatrix.sync.aligned.m8n8.x4.shared.b16 {%0,%1,%2,%3}, [%4];"
                 : "=r"(r[0]), "=r"(r[1]), "=r"(r[2]), "=r"(r[3]) : "r"(ad));
}
__device__ __forceinline__ void ldm_x4t(uint32_t* r, uint32_t ad) {
    asm volatile("ldmatrix.sync.aligned.m8n8.x4.trans.shared.b16 {%0,%1,%2,%3}, [%4];"
                 : "=r"(r[0]), "=r"(r[1]), "=r"(r[2]), "=r"(r[3]) : "r"(ad));
}

__global__ void __launch_bounds__(128, 2)
gemm_kernel(float* __restrict__ C) {
    extern __shared__ char S[];

    const int tid  = threadIdx.x;
    const int lane = tid & 31;
    const int warp = tid >> 5;
    const int wm = warp * 32;          // 4 warps along M, each owns 32x64
    const int g  = lane >> 2;
    const int c2 = (lane & 3) * 2;

    const int m0 = blockIdx.x * BM;
    const int n0 = blockIdx.y * BN;

    const __half* Ag = g_A + (size_t)m0 * KTOT;
    const __half* Bg = g_GB + (size_t)(n0 >> 6) * 32 * 4096;  // per-kt 8KB tiles

    const int lr = lane & 15;
    const int hc = (lane >> 4) * 8;

    float acc[2][8][4];
#pragma unroll
    for (int mi = 0; mi < 2; mi++)
#pragma unroll
        for (int jn = 0; jn < 8; jn++)
#pragma unroll
            for (int q = 0; q < 4; q++) acc[mi][jn][q] = 0.f;

    const int NK = KTOT / BK;   // 32

    // prologue: issue stages 0 and 1
#pragma unroll
    for (int st = 0; st < NSTAGE - 1; st++) {
        char* base = S + st * STG;
#pragma unroll
        for (int j = 0; j < 8; j++) {
            int c = j * 128 + tid;
            int r = c >> 3, co = c & 7;
            CP_ASYNC16(smem_addr(base + (r * AKP + co * 8) * 2),
                       Ag + (size_t)r * KTOT + st * BK + co * 8);
        }
#pragma unroll
        for (int j = 0; j < 4; j++) {
            int c = j * 128 + tid;
            CP_ASYNC16(smem_addr(base + A_ST + ((c >> 3) * BNP + (c & 7) * 8) * 2),
                       Bg + (size_t)st * 4096 + c * 8);
        }
        CP_COMMIT();
    }

    for (int kt = 0; kt < NK; kt++) {
        if (kt < NK - 1) { CP_WAIT(1); } else { CP_WAIT(0); }
        __syncthreads();

        // issue stage kt+2
        if (kt + 2 < NK) {
            char* base = S + ((kt + 2) % NSTAGE) * STG;
#pragma unroll
            for (int j = 0; j < 8; j++) {
                int c = j * 128 + tid;
                int r = c >> 3, co = c & 7;
                CP_ASYNC16(smem_addr(base + (r * AKP + co * 8) * 2),
                           Ag + (size_t)r * KTOT + (kt + 2) * BK + co * 8);
            }
#pragma unroll
            for (int j = 0; j < 4; j++) {
                int c = j * 128 + tid;
                CP_ASYNC16(smem_addr(base + A_ST +
                                     ((c >> 3) * BNP + (c & 7) * 8) * 2),
                           Bg + (size_t)(kt + 2) * 4096 + c * 8);
            }
            CP_COMMIT();
        }

        const __half* Asb = (const __half*)(S + (kt % NSTAGE) * STG);
        const __half* Bsb = (const __half*)(S + (kt % NSTAGE) * STG + A_ST);

        // register double-buffered fragments: load s+1 before MMAs of s
        uint32_t af[2][2][4], bf[2][4][4];
#pragma unroll
        for (int mi = 0; mi < 2; mi++)
            ldm_x4(af[0][mi], smem_addr(Asb + (wm + mi * 16 + lr) * AKP + hc));
#pragma unroll
        for (int j4 = 0; j4 < 4; j4++)
            ldm_x4t(bf[0][j4], smem_addr(Bsb + lr * BNP + j4 * 16 + hc));

#pragma unroll
        for (int s = 0; s < 4; s++) {
            const int cur = s & 1, nxt = cur ^ 1;
            if (s < 3) {
#pragma unroll
                for (int mi = 0; mi < 2; mi++)
                    ldm_x4(af[nxt][mi], smem_addr(Asb + (wm + mi * 16 + lr) * AKP
                                                      + (s + 1) * 16 + hc));
#pragma unroll
                for (int j4 = 0; j4 < 4; j4++)
                    ldm_x4t(bf[nxt][j4], smem_addr(Bsb + ((s + 1) * 16 + lr) * BNP
                                                       + j4 * 16 + hc));
            }
#pragma unroll
            for (int mi = 0; mi < 2; mi++)
#pragma unroll
                for (int j4 = 0; j4 < 4; j4++) {
                    mma16816(acc[mi][2 * j4 + 0], af[cur][mi],
                             bf[cur][j4][0], bf[cur][j4][1]);
                    mma16816(acc[mi][2 * j4 + 1], af[cur][mi],
                             bf[cur][j4][2], bf[cur][j4][3]);
                }
        }
        __syncthreads();
    }

    // epilogue: warp owns rows [wm, wm+32) x all 64 cols
#pragma unroll
    for (int mi = 0; mi < 2; mi++) {
#pragma unroll
        for (int jn = 0; jn < 8; jn++) {
            int row = m0 + wm + mi * 16 + g;
            int col = n0 + jn * 8 + c2;
            float2 v0 = make_float2(acc[mi][jn][0], acc[mi][jn][1]);
            float2 v1 = make_float2(acc[mi][jn][2], acc[mi][jn][3]);
            *(float2*)&C[(size_t)row * NTOT + col]       = v0;
            *(float2*)&C[(size_t)(row + 8) * NTOT + col] = v1;
        }
    }
}

// ---------------------------------------------------------------------------
extern "C" void kernel_launch(void* const* d_in, const int* in_sizes, int n_in,
                              void* d_out, int out_size) {
    (void)in_sizes; (void)n_in; (void)out_size;
    const float* x     = (const float*)d_in[0];   // (4,2048,256) f32
    const float* coeff = (const float*)d_in[1];   // (8,13) f32
    const float* gw    = (const float*)d_in[2];   // (256,256,8) f32
    float* out = (float*)d_out;                   // (4,2048,256) f32

    cudaFuncSetAttribute(gemm_kernel,
                         cudaFuncAttributeMaxDynamicSharedMemorySize, SMEM_NEED);

    prep_kernel<<<256 + MTOT * IN_CH / 256, 256>>>(gw, x, coeff);
    dim3 grid(MTOT / BM, NTOT / BN);
    gemm_kernel<<<grid, 128, SMEM_NEED>>>(out);
}